// round 3
// baseline (speedup 1.0000x reference)
#include <cuda_runtime.h>
#include <cuda_fp16.h>
#include <cstdint>

#define TB      512
#define MROWS   128
#define HID     128
#define TSTEPS  28
#define XROW    784
#define GRID    512          // 65536 / 128

// SMEM layout (half elements, row stride 168 = 336 B -> conflict-free ldmatrix)
#define OFF_A      2048                 // A [128][168] half = 43008 B  (h | x | 1 | pad)
#define OFF_W      45056                // W [512][168] half = 172032 B (gate-major rows)
#define SMEM_TOTAL 217088
#define ASTRIDE    168

__device__ __forceinline__ uint32_t su32(const void* p) {
    uint32_t a;
    asm("{ .reg .u64 t; cvta.to.shared.u64 t, %1; cvt.u32.u64 %0, t; }" : "=r"(a) : "l"(p));
    return a;
}

#define LDSM4(R0, R1, R2, R3, ADDR)                                            \
    asm volatile("ldmatrix.sync.aligned.m8n8.x4.shared.b16 {%0,%1,%2,%3}, [%4];" \
                 : "=r"(R0), "=r"(R1), "=r"(R2), "=r"(R3) : "r"(ADDR))

#define MMA(D, A0, A1, A2, A3, B0, B1)                                         \
    asm volatile("mma.sync.aligned.m16n8k16.row.col.f32.f16.f16.f32 "          \
                 "{%0,%1,%2,%3}, {%4,%5,%6,%7}, {%8,%9}, {%0,%1,%2,%3};"       \
                 : "+f"((D)[0]), "+f"((D)[1]), "+f"((D)[2]), "+f"((D)[3])      \
                 : "r"(A0), "r"(A1), "r"(A2), "r"(A3), "r"(B0), "r"(B1))

__device__ __forceinline__ float ftanh(float v) {
    float r;
    asm("tanh.approx.f32 %0, %1;" : "=f"(r) : "f"(v));
    return r;
}
__device__ __forceinline__ float fsig(float v) {
    return fmaf(0.5f, ftanh(0.5f * v), 0.5f);
}

__global__ void __launch_bounds__(TB, 1)
lstm_kernel(const float* __restrict__ x,
            const float* __restrict__ Wf, const float* __restrict__ bf_,
            const float* __restrict__ Wi, const float* __restrict__ bi_,
            const float* __restrict__ Wc, const float* __restrict__ bc_,
            const float* __restrict__ Wo, const float* __restrict__ bo_,
            float* __restrict__ out)
{
    extern __shared__ char smem[];
    const uint32_t sbase = su32(smem);
    half* const Ah = (half*)(smem + OFF_A);
    half* const Wh = (half*)(smem + OFF_W);

    const int tid = threadIdx.x;
    const int lane = tid & 31, wid = tid >> 5;
    const int warp_m = wid >> 1;          // 8 m-warps, 16 rows each
    const int warp_n = wid & 1;           // 2 n-warps, 16 j each per chunk
    const size_t row_g0 = (size_t)blockIdx.x * MROWS;

    // ---- zero A and W regions ----
    {
        uint32_t* za = (uint32_t*)(smem + OFF_A);
        for (int i = tid; i < 21504; i += TB) za[i] = 0u;
        uint32_t* zw = (uint32_t*)(smem + OFF_W);
        for (int i = tid; i < 43008; i += TB) zw[i] = 0u;
    }
    __syncthreads();

    // ---- A: bias column = 1.0 ----
    if (tid < MROWS) Ah[tid * ASTRIDE + 156] = __float2half(1.0f);

    // ---- A: x_0 tile ----
    const int row_x = tid >> 2;
    const int xc0 = (tid & 3) * 7;
    {
        const float* xp = x + (row_g0 + row_x) * XROW + xc0;
        #pragma unroll
        for (int u = 0; u < 7; u++)
            Ah[row_x * ASTRIDE + 128 + xc0 + u] = __float2half(__ldg(xp + u));
    }

    // ---- W: rows n = g*128 + j (f,i,n,o), cols 0..155 weights, 156 = bias ----
    for (int idx = tid; idx < 4 * 128 * 156; idx += TB) {
        int g = idx / 19968;
        int rem = idx - g * 19968;
        int hrow = rem / 156;
        int k = rem - hrow * 156;
        const float* Wg = (g == 0) ? Wf : (g == 1) ? Wi : (g == 2) ? Wc : Wo;
        Wh[((g << 7) + hrow) * ASTRIDE + k] = __float2half(Wg[rem]);
    }
    {
        int g = tid >> 7, j = tid & 127;
        const float* bp = (g == 0) ? bf_ : (g == 1) ? bi_ : (g == 2) ? bc_ : bo_;
        Wh[tid * ASTRIDE + 156] = __float2half(bp[j]);
    }
    __syncthreads();

    // ---- per-thread ldmatrix base addresses ----
    // A frag (m16k16): lanes 0-15 -> rows m0+(l&15), k0 ; lanes 16-31 -> same rows, k0+8
    const uint32_t a_addr0 = sbase + OFF_A
        + (uint32_t)(warp_m * 16 + (lane & 15)) * (ASTRIDE * 2)
        + (uint32_t)((lane >> 4) * 8) * 2;
    // B frag (n16k16): nrow = (l&7) + ((l>>4)<<3), kadd = ((l>>3)&1)*8
    const uint32_t bbase = sbase + OFF_W
        + (uint32_t)(warp_n * 16 + ((lane & 7) + ((lane >> 4) << 3))) * (ASTRIDE * 2)
        + (uint32_t)(((lane >> 3) & 1) * 8) * 2;

    float cst[32];
    #pragma unroll
    for (int i = 0; i < 32; i++) cst[i] = 0.0f;
    half2 hst[16];

    const int row0 = warp_m * 16 + (lane >> 2);     // m=0 row; m=1 adds 8
    const int jbase = warp_n * 16 + (lane & 3) * 2; // + ch*32 + jh*8

    #pragma unroll 1
    for (int t = 0; t < TSTEPS; t++) {
        // prefetch x_{t+1}
        float xr[7];
        const bool havex = (t + 1 < TSTEPS);
        if (havex) {
            const float* xp = x + (row_g0 + row_x) * XROW + (size_t)(t + 1) * 28 + xc0;
            #pragma unroll
            for (int u = 0; u < 7; u++) xr[u] = __ldg(xp + u);
        }
        const bool last = (t == TSTEPS - 1);

        #pragma unroll
        for (int ch = 0; ch < 4; ch++) {
            float acc[8][4];
            #pragma unroll
            for (int q = 0; q < 8; q++)
                #pragma unroll
                for (int r = 0; r < 4; r++) acc[q][r] = 0.0f;

            #pragma unroll
            for (int ks = 0; ks < 10; ks++) {
                uint32_t a0, a1, a2, a3;
                LDSM4(a0, a1, a2, a3, a_addr0 + ks * 32);
                #pragma unroll
                for (int g = 0; g < 4; g++) {
                    uint32_t b0, b1, b2, b3;
                    LDSM4(b0, b1, b2, b3,
                          bbase + (uint32_t)(g * 43008 + ch * 10752 + ks * 32));
                    MMA(acc[g * 2 + 0], a0, a1, a2, a3, b0, b1);
                    MMA(acc[g * 2 + 1], a0, a1, a2, a3, b2, b3);
                }
            }

            // epilogue for this chunk's 32 hidden units
            #pragma unroll
            for (int jh = 0; jh < 2; jh++) {
                #pragma unroll
                for (int m = 0; m < 2; m++) {
                    float hv0, hv1;
                    #pragma unroll
                    for (int jc = 0; jc < 2; jc++) {
                        const int ai = m * 2 + jc;
                        float fv = acc[0 + jh][ai];
                        float iv = acc[2 + jh][ai];
                        float nv = acc[4 + jh][ai];
                        float ov = acc[6 + jh][ai];
                        float fs = fsig(fv), is = fsig(iv), os = fsig(ov);
                        float ns = ftanh(nv);
                        const int ci = ch * 8 + (jh * 2 + m) * 2 + jc;
                        float cc = fmaf(cst[ci], fs, is * ns);
                        cst[ci] = cc;
                        float hh = os * ftanh(cc);
                        if (jc == 0) hv0 = hh; else hv1 = hh;
                    }
                    if (last) {
                        const int rowm = row0 + m * 8;
                        const int j = ch * 32 + jbase + jh * 8;
                        *(float2*)(out + (row_g0 + rowm) * HID + j) =
                            make_float2(hv0, hv1);
                    } else {
                        hst[ch * 4 + jh * 2 + m] = __floats2half2_rn(hv0, hv1);
                    }
                }
            }
        }

        __syncthreads();   // all A reads done before anyone rewrites A

        if (!last) {
            // write h_{t+1}
            #pragma unroll
            for (int ch = 0; ch < 4; ch++)
                #pragma unroll
                for (int jh = 0; jh < 2; jh++)
                    #pragma unroll
                    for (int m = 0; m < 2; m++) {
                        const int rowm = row0 + m * 8;
                        const int j = ch * 32 + jbase + jh * 8;
                        *(half2*)&Ah[rowm * ASTRIDE + j] = hst[ch * 4 + jh * 2 + m];
                    }
            // write x_{t+1}
            #pragma unroll
            for (int u = 0; u < 7; u++)
                Ah[row_x * ASTRIDE + 128 + xc0 + u] = __float2half(xr[u]);
        }

        __syncthreads();   // A complete before next step's ldmatrix
    }
}

extern "C" void kernel_launch(void* const* d_in, const int* in_sizes, int n_in,
                              void* d_out, int out_size) {
    (void)in_sizes; (void)n_in; (void)out_size;
    cudaFuncSetAttribute(lstm_kernel, cudaFuncAttributeMaxDynamicSharedMemorySize,
                         SMEM_TOTAL);
    lstm_kernel<<<GRID, TB, SMEM_TOTAL>>>(
        (const float*)d_in[0],
        (const float*)d_in[1], (const float*)d_in[2],
        (const float*)d_in[3], (const float*)d_in[4],
        (const float*)d_in[5], (const float*)d_in[6],
        (const float*)d_in[7], (const float*)d_in[8],
        (float*)d_out);
}

// round 4
// speedup vs baseline: 1.2516x; 1.2516x over previous
#include <cuda_runtime.h>
#include <cuda_fp16.h>
#include <cstdint>

#define TB      512
#define MROWS   128
#define HID     128
#define TSTEPS  28
#define XROW    784
#define NTILES  512          // 65536 / 128
#define GRID    148          // persistent

// SMEM layout (half elements, row stride 168 = 336 B -> conflict-free ldmatrix)
#define OFF_A      2048                 // A [128][168] half  (h | x | 1 | pad)
#define OFF_W      45056                // W [512][168] half  (gate-major rows)
#define SMEM_TOTAL 217088
#define ASTRIDE    168

__device__ __forceinline__ uint32_t su32(const void* p) {
    uint32_t a;
    asm("{ .reg .u64 t; cvta.to.shared.u64 t, %1; cvt.u32.u64 %0, t; }" : "=r"(a) : "l"(p));
    return a;
}

#define LDSM4(R0, R1, R2, R3, ADDR)                                            \
    asm volatile("ldmatrix.sync.aligned.m8n8.x4.shared.b16 {%0,%1,%2,%3}, [%4];" \
                 : "=r"(R0), "=r"(R1), "=r"(R2), "=r"(R3) : "r"(ADDR))

#define MMA(D, A0, A1, A2, A3, B0, B1)                                         \
    asm volatile("mma.sync.aligned.m16n8k16.row.col.f32.f16.f16.f32 "          \
                 "{%0,%1,%2,%3}, {%4,%5,%6,%7}, {%8,%9}, {%0,%1,%2,%3};"       \
                 : "+f"((D)[0]), "+f"((D)[1]), "+f"((D)[2]), "+f"((D)[3])      \
                 : "r"(A0), "r"(A1), "r"(A2), "r"(A3), "r"(B0), "r"(B1))

// 64-thread barrier scoped to one m-pair (warps 2*warp_m, 2*warp_m+1)
#define PAIRBAR() asm volatile("bar.sync %0, 64;" :: "r"(warp_m + 1) : "memory")

__device__ __forceinline__ float ftanh(float v) {
    float r;
    asm("tanh.approx.f32 %0, %1;" : "=f"(r) : "f"(v));
    return r;
}
__device__ __forceinline__ float fsig(float v) {
    return fmaf(0.5f, ftanh(0.5f * v), 0.5f);
}

__global__ void __launch_bounds__(TB, 1)
lstm_kernel(const float* __restrict__ x,
            const float* __restrict__ Wf, const float* __restrict__ bf_,
            const float* __restrict__ Wi, const float* __restrict__ bi_,
            const float* __restrict__ Wc, const float* __restrict__ bc_,
            const float* __restrict__ Wo, const float* __restrict__ bo_,
            float* __restrict__ out)
{
    extern __shared__ char smem[];
    const uint32_t sbase = su32(smem);
    half* const Ah = (half*)(smem + OFF_A);
    half* const Wh = (half*)(smem + OFF_W);

    const int tid  = threadIdx.x;
    const int lane = tid & 31, wid = tid >> 5;
    const int warp_m = wid >> 1;          // 8 m-pairs, 16 rows each
    const int warp_n = wid & 1;           // 2 n-warps per pair
    const int ptid   = tid & 63;          // thread index within the pair
    const int pr0    = warp_m * 16;       // pair's first A row
    const int rowx   = pr0 + (ptid >> 2); // pair-local x row
    const int xc0    = (ptid & 3) * 7;    // x column group

    // ---- one-time init: zero A + W pads, load W + biases, bias column ----
    {
        uint32_t* za = (uint32_t*)(smem + OFF_A);
        for (int i = tid; i < 21504; i += TB) za[i] = 0u;
        uint32_t* zw = (uint32_t*)(smem + OFF_W);
        for (int i = tid; i < 43008; i += TB) zw[i] = 0u;
    }
    __syncthreads();
    for (int idx = tid; idx < 4 * 128 * 156; idx += TB) {
        int g = idx / 19968;
        int rem = idx - g * 19968;
        int hrow = rem / 156;
        int k = rem - hrow * 156;
        const float* Wg = (g == 0) ? Wf : (g == 1) ? Wi : (g == 2) ? Wc : Wo;
        Wh[((g << 7) + hrow) * ASTRIDE + k] = __float2half(Wg[rem]);
    }
    {
        int g = tid >> 7, j = tid & 127;
        const float* bp = (g == 0) ? bf_ : (g == 1) ? bi_ : (g == 2) ? bc_ : bo_;
        Wh[tid * ASTRIDE + 156] = __float2half(bp[j]);
    }
    if (tid < MROWS) Ah[tid * ASTRIDE + 156] = __float2half(1.0f);
    __syncthreads();

    // ---- ldmatrix base addresses ----
    const uint32_t a_addr0 = sbase + OFF_A
        + (uint32_t)(pr0 + (lane & 15)) * (ASTRIDE * 2)
        + (uint32_t)((lane >> 4) * 8) * 2;
    const uint32_t bbase = sbase + OFF_W
        + (uint32_t)(warp_n * 16 + ((lane & 7) + ((lane >> 4) << 3))) * (ASTRIDE * 2)
        + (uint32_t)(((lane >> 3) & 1) * 8) * 2;

    const int row0  = pr0 + (lane >> 2);            // m=0 row; m=1 adds 8
    const int jbase = warp_n * 16 + (lane & 3) * 2; // + ch*32 + jh*8

    float cst[32];
    half2 hst[16];

    // ================= persistent tile loop =================
    #pragma unroll 1
    for (int tile = blockIdx.x; tile < NTILES; tile += GRID) {
        const size_t row_g0 = (size_t)tile * MROWS;

        // ---- per-tile prologue (pair-scoped): h0 = 0, load x0, c0 = 0 ----
        for (int i = ptid; i < 16 * 64; i += 64)
            ((uint32_t*)(Ah + (size_t)(pr0 + (i >> 6)) * ASTRIDE))[i & 63] = 0u;
        {
            const float* xp = x + (row_g0 + rowx) * XROW + xc0;
            #pragma unroll
            for (int u = 0; u < 7; u++)
                Ah[rowx * ASTRIDE + 128 + xc0 + u] = __float2half(__ldg(xp + u));
        }
        #pragma unroll
        for (int i = 0; i < 32; i++) cst[i] = 0.0f;
        PAIRBAR();

        #pragma unroll 1
        for (int t = 0; t < TSTEPS; t++) {
            // prefetch x_{t+1}
            float xr[7];
            const bool last = (t == TSTEPS - 1);
            if (!last) {
                const float* xp = x + (row_g0 + rowx) * XROW + (size_t)(t + 1) * 28 + xc0;
                #pragma unroll
                for (int u = 0; u < 7; u++) xr[u] = __ldg(xp + u);
            }

            #pragma unroll
            for (int ch = 0; ch < 4; ch++) {
                float acc[8][4];
                #pragma unroll
                for (int q = 0; q < 8; q++)
                    #pragma unroll
                    for (int r = 0; r < 4; r++) acc[q][r] = 0.0f;

                #pragma unroll
                for (int ks = 0; ks < 10; ks++) {
                    uint32_t a0, a1, a2, a3;
                    LDSM4(a0, a1, a2, a3, a_addr0 + ks * 32);
                    #pragma unroll
                    for (int g = 0; g < 4; g++) {
                        uint32_t b0, b1, b2, b3;
                        LDSM4(b0, b1, b2, b3,
                              bbase + (uint32_t)(g * 43008 + ch * 10752 + ks * 32));
                        MMA(acc[g * 2 + 0], a0, a1, a2, a3, b0, b1);
                        MMA(acc[g * 2 + 1], a0, a1, a2, a3, b2, b3);
                    }
                }

                // epilogue: 32 hidden units of this chunk
                #pragma unroll
                for (int jh = 0; jh < 2; jh++) {
                    #pragma unroll
                    for (int m = 0; m < 2; m++) {
                        float hv0, hv1;
                        #pragma unroll
                        for (int jc = 0; jc < 2; jc++) {
                            const int ai = m * 2 + jc;
                            float fv = acc[0 + jh][ai];
                            float iv = acc[2 + jh][ai];
                            float nv = acc[4 + jh][ai];
                            float ov = acc[6 + jh][ai];
                            float fs = fsig(fv), is = fsig(iv), os = fsig(ov);
                            float ns = ftanh(nv);
                            const int ci = ch * 8 + (jh * 2 + m) * 2 + jc;
                            float cc = fmaf(cst[ci], fs, is * ns);
                            cst[ci] = cc;
                            float hh = os * ftanh(cc);
                            if (jc == 0) hv0 = hh; else hv1 = hh;
                        }
                        if (last) {
                            const int rowm = row0 + m * 8;
                            const int j = ch * 32 + jbase + jh * 8;
                            *(float2*)(out + (row_g0 + rowm) * HID + j) =
                                make_float2(hv0, hv1);
                        } else {
                            hst[ch * 4 + jh * 2 + m] = __floats2half2_rn(hv0, hv1);
                        }
                    }
                }
            }

            PAIRBAR();   // pair's A reads done before pair rewrites A

            if (!last) {
                #pragma unroll
                for (int ch = 0; ch < 4; ch++)
                    #pragma unroll
                    for (int jh = 0; jh < 2; jh++)
                        #pragma unroll
                        for (int m = 0; m < 2; m++) {
                            const int rowm = row0 + m * 8;
                            const int j = ch * 32 + jbase + jh * 8;
                            *(half2*)&Ah[rowm * ASTRIDE + j] = hst[ch * 4 + jh * 2 + m];
                        }
                #pragma unroll
                for (int u = 0; u < 7; u++)
                    Ah[rowx * ASTRIDE + 128 + xc0 + u] = __float2half(xr[u]);
            }

            PAIRBAR();   // pair's A writes visible before next step's ldsm
        }
    }
}

extern "C" void kernel_launch(void* const* d_in, const int* in_sizes, int n_in,
                              void* d_out, int out_size) {
    (void)in_sizes; (void)n_in; (void)out_size;
    cudaFuncSetAttribute(lstm_kernel, cudaFuncAttributeMaxDynamicSharedMemorySize,
                         SMEM_TOTAL);
    lstm_kernel<<<GRID, TB, SMEM_TOTAL>>>(
        (const float*)d_in[0],
        (const float*)d_in[1], (const float*)d_in[2],
        (const float*)d_in[3], (const float*)d_in[4],
        (const float*)d_in[5], (const float*)d_in[6],
        (const float*)d_in[7], (const float*)d_in[8],
        (float*)d_out);
}

// round 5
// speedup vs baseline: 1.2641x; 1.0100x over previous
#include <cuda_runtime.h>
#include <cuda_fp16.h>
#include <cstdint>

#define TB      256
#define MROWS   64
#define HID     128
#define TSTEPS  28
#define XROW    784
#define NTILES  1024         // 65536 / 64
#define GRID    148          // persistent

// SMEM (half elems, row stride 168 = 336 B -> conflict-free ldmatrix)
#define OFF_A      1024                 // A [64][168] half  (h | x | 1 | pad)
#define OFF_W      22528                // W [512][168] half (gate-major rows)
#define SMEM_TOTAL 194560
#define ASTRIDE    168

__device__ __forceinline__ uint32_t su32(const void* p) {
    uint32_t a;
    asm("{ .reg .u64 t; cvta.to.shared.u64 t, %1; cvt.u32.u64 %0, t; }" : "=r"(a) : "l"(p));
    return a;
}

#define LDSM4(R0, R1, R2, R3, ADDR)                                            \
    asm volatile("ldmatrix.sync.aligned.m8n8.x4.shared.b16 {%0,%1,%2,%3}, [%4];" \
                 : "=r"(R0), "=r"(R1), "=r"(R2), "=r"(R3) : "r"(ADDR))

#define MMA(D, A0, A1, A2, A3, B0, B1)                                         \
    asm volatile("mma.sync.aligned.m16n8k16.row.col.f32.f16.f16.f32 "          \
                 "{%0,%1,%2,%3}, {%4,%5,%6,%7}, {%8,%9}, {%0,%1,%2,%3};"       \
                 : "+f"((D)[0]), "+f"((D)[1]), "+f"((D)[2]), "+f"((D)[3])      \
                 : "r"(A0), "r"(A1), "r"(A2), "r"(A3), "r"(B0), "r"(B1))

// 128-thread barrier scoped to one row-group (warps 4*rg .. 4*rg+3)
#define GRPBAR() asm volatile("bar.sync %0, 128;" :: "r"(rg + 1) : "memory")

__device__ __forceinline__ float ftanh(float v) {
    float r;
    asm("tanh.approx.f32 %0, %1;" : "=f"(r) : "f"(v));
    return r;
}
__device__ __forceinline__ float fsig(float v) {
    return fmaf(0.5f, ftanh(0.5f * v), 0.5f);
}

__global__ void __launch_bounds__(TB, 1)
lstm_kernel(const float* __restrict__ x,
            const float* __restrict__ Wf, const float* __restrict__ bf_,
            const float* __restrict__ Wi, const float* __restrict__ bi_,
            const float* __restrict__ Wc, const float* __restrict__ bc_,
            const float* __restrict__ Wo, const float* __restrict__ bo_,
            float* __restrict__ out)
{
    extern __shared__ char smem[];
    const uint32_t sbase = su32(smem);
    half* const Ah = (half*)(smem + OFF_A);
    half* const Wh = (half*)(smem + OFF_W);

    const int tid  = threadIdx.x;
    const int lane = tid & 31, wid = tid >> 5;
    const int rg   = wid >> 2;            // 2 row-groups, 32 rows each
    const int wn   = wid & 3;             // 4 j-warps: j block = wn*32
    const int gtid = tid & 127;           // thread index within row-group
    const int gr0  = rg * 32;             // group's first A row
    const int rowx = gr0 + (gtid >> 2);   // group-local x row
    const int xc0  = (gtid & 3) * 7;      // x column group

    // ---- one-time init ----
    {
        uint32_t* za = (uint32_t*)(smem + OFF_A);
        for (int i = tid; i < 5376; i += TB) za[i] = 0u;
        uint32_t* zw = (uint32_t*)(smem + OFF_W);
        for (int i = tid; i < 43008; i += TB) zw[i] = 0u;
    }
    __syncthreads();
    for (int idx = tid; idx < 4 * 128 * 156; idx += TB) {
        int g = idx / 19968;
        int rem = idx - g * 19968;
        int hrow = rem / 156;
        int k = rem - hrow * 156;
        const float* Wg = (g == 0) ? Wf : (g == 1) ? Wi : (g == 2) ? Wc : Wo;
        Wh[((g << 7) + hrow) * ASTRIDE + k] = __float2half(Wg[rem]);
    }
    for (int n = tid; n < 512; n += TB) {
        int g = n >> 7, j = n & 127;
        const float* bp = (g == 0) ? bf_ : (g == 1) ? bi_ : (g == 2) ? bc_ : bo_;
        Wh[n * ASTRIDE + 156] = __float2half(bp[j]);
    }
    if (tid < MROWS) Ah[tid * ASTRIDE + 156] = __float2half(1.0f);
    __syncthreads();

    // ---- ldmatrix base addresses ----
    // A m16k16 frag: lanes 0-15 rows, lanes 16-31 same rows k+8
    const uint32_t a_addr0 = sbase + OFF_A
        + (uint32_t)(gr0 + (lane & 15)) * (ASTRIDE * 2)
        + (uint32_t)((lane >> 4) * 8) * 2;
    // B n16k16 frag base (rows n = g*128 + wn*32 + ch2*16 ...)
    const uint32_t bbase = sbase + OFF_W
        + (uint32_t)(wn * 32 + ((lane & 7) + ((lane >> 4) << 3))) * (ASTRIDE * 2)
        + (uint32_t)(((lane >> 3) & 1) * 8) * 2;

    const int row0c = gr0 + (lane >> 2);         // + mf*16 + mi*8
    const int jb0   = wn * 32 + (lane & 3) * 2;  // + ch2*16 + n8*8 (+jc)

    float cst[32];
    half2 hst[16];

    // ================= persistent tile loop =================
    #pragma unroll 1
    for (int tile = blockIdx.x; tile < NTILES; tile += GRID) {
        const size_t row_g0 = (size_t)tile * MROWS;

        // ---- per-tile prologue (group-scoped): h0 = 0, x0, c0 = 0 ----
        for (int i = gtid; i < 32 * 64; i += 128)
            ((uint32_t*)(Ah + (size_t)(gr0 + (i >> 6)) * ASTRIDE))[i & 63] = 0u;
        {
            const float* xp = x + (row_g0 + rowx) * XROW + xc0;
            #pragma unroll
            for (int u = 0; u < 7; u++)
                Ah[rowx * ASTRIDE + 128 + xc0 + u] = __float2half(__ldg(xp + u));
        }
        #pragma unroll
        for (int i = 0; i < 32; i++) cst[i] = 0.0f;
        GRPBAR();

        #pragma unroll 1
        for (int t = 0; t < TSTEPS; t++) {
            const bool last = (t == TSTEPS - 1);

            // prefetch x_{t+1} (overlaps everything below)
            float xr[7];
            if (!last) {
                const float* xp = x + (row_g0 + rowx) * XROW + (size_t)(t + 1) * 28 + xc0;
                #pragma unroll
                for (int u = 0; u < 7; u++) xr[u] = __ldg(xp + u);
            }

            // ---- hoist ALL A fragments for this step (20 LDSM) ----
            uint32_t af[10][2][4];
            #pragma unroll
            for (int ks = 0; ks < 10; ks++)
                #pragma unroll
                for (int mf = 0; mf < 2; mf++)
                    LDSM4(af[ks][mf][0], af[ks][mf][1], af[ks][mf][2], af[ks][mf][3],
                          a_addr0 + (uint32_t)(mf * 16 * ASTRIDE * 2 + ks * 32));

            GRPBAR();   // all group A reads done -> A is writable after this

            // ---- 2 sub-chunks of 16 hidden units ----
            #pragma unroll
            for (int ch2 = 0; ch2 < 2; ch2++) {
                float acc[4][2][2][4];   // [gate][n8][mf][reg]
                #pragma unroll
                for (int g = 0; g < 4; g++)
                    #pragma unroll
                    for (int n8 = 0; n8 < 2; n8++)
                        #pragma unroll
                        for (int mf = 0; mf < 2; mf++)
                            #pragma unroll
                            for (int r = 0; r < 4; r++) acc[g][n8][mf][r] = 0.0f;

                #pragma unroll
                for (int ks = 0; ks < 10; ks++) {
                    #pragma unroll
                    for (int g = 0; g < 4; g++) {
                        uint32_t b0, b1, b2, b3;
                        LDSM4(b0, b1, b2, b3,
                              bbase + (uint32_t)(g * 43008 + ch2 * (16 * ASTRIDE * 2)
                                                 + ks * 32));
                        #pragma unroll
                        for (int mf = 0; mf < 2; mf++) {
                            MMA(acc[g][0][mf], af[ks][mf][0], af[ks][mf][1],
                                af[ks][mf][2], af[ks][mf][3], b0, b1);
                            MMA(acc[g][1][mf], af[ks][mf][0], af[ks][mf][1],
                                af[ks][mf][2], af[ks][mf][3], b2, b3);
                        }
                    }
                }

                // ---- epilogue: 16 j x 32 m handled by this warp ----
                #pragma unroll
                for (int n8 = 0; n8 < 2; n8++) {
                    #pragma unroll
                    for (int mf = 0; mf < 2; mf++) {
                        #pragma unroll
                        for (int mi = 0; mi < 2; mi++) {
                            float hv0, hv1;
                            #pragma unroll
                            for (int jc = 0; jc < 2; jc++) {
                                const int ai = mi * 2 + jc;
                                float fv = acc[0][n8][mf][ai];
                                float iv = acc[1][n8][mf][ai];
                                float nv = acc[2][n8][mf][ai];
                                float ov = acc[3][n8][mf][ai];
                                float fs = fsig(fv), is = fsig(iv), os = fsig(ov);
                                float ns = ftanh(nv);
                                const int ci = (((ch2 * 2 + n8) * 2 + mf) * 2 + mi) * 2 + jc;
                                float cc = fmaf(cst[ci], fs, is * ns);
                                cst[ci] = cc;
                                float hh = os * ftanh(cc);
                                if (jc == 0) hv0 = hh; else hv1 = hh;
                            }
                            const int hi = ((ch2 * 2 + n8) * 2 + mf) * 2 + mi;
                            if (last) {
                                const int rowm = row0c + mf * 16 + mi * 8;
                                const int j = jb0 + ch2 * 16 + n8 * 8;
                                *(float2*)(out + (row_g0 + rowm) * HID + j) =
                                    make_float2(hv0, hv1);
                            } else {
                                hst[hi] = __floats2half2_rn(hv0, hv1);
                            }
                        }
                    }
                }
            }

            if (!last) {
                // write h_{t+1} and x_{t+1} into A
                #pragma unroll
                for (int ch2 = 0; ch2 < 2; ch2++)
                    #pragma unroll
                    for (int n8 = 0; n8 < 2; n8++)
                        #pragma unroll
                        for (int mf = 0; mf < 2; mf++)
                            #pragma unroll
                            for (int mi = 0; mi < 2; mi++) {
                                const int rowm = row0c + mf * 16 + mi * 8;
                                const int j = jb0 + ch2 * 16 + n8 * 8;
                                *(half2*)&Ah[rowm * ASTRIDE + j] =
                                    hst[((ch2 * 2 + n8) * 2 + mf) * 2 + mi];
                            }
                #pragma unroll
                for (int u = 0; u < 7; u++)
                    Ah[rowx * ASTRIDE + 128 + xc0 + u] = __float2half(xr[u]);
            }

            GRPBAR();   // A writes visible before next step's ldsm
        }
    }
}

extern "C" void kernel_launch(void* const* d_in, const int* in_sizes, int n_in,
                              void* d_out, int out_size) {
    (void)in_sizes; (void)n_in; (void)out_size;
    cudaFuncSetAttribute(lstm_kernel, cudaFuncAttributeMaxDynamicSharedMemorySize,
                         SMEM_TOTAL);
    lstm_kernel<<<GRID, TB, SMEM_TOTAL>>>(
        (const float*)d_in[0],
        (const float*)d_in[1], (const float*)d_in[2],
        (const float*)d_in[3], (const float*)d_in[4],
        (const float*)d_in[5], (const float*)d_in[6],
        (const float*)d_in[7], (const float*)d_in[8],
        (float*)d_out);
}

// round 7
// speedup vs baseline: 1.3802x; 1.0918x over previous
#include <cuda_runtime.h>
#include <cuda_fp16.h>
#include <cstdint>

#define TB      256
#define GRID    148
#define HID     128
#define TSTEPS  28
#define XROW    784
#define NTASKS  4096         // 65536 / 16 rows per warp-task
#define NWARPS  (GRID * 8)
#define WSTR    168          // W row stride in halves (336 B, conflict-free ldsm)
#define SMEM_TOTAL (512 * WSTR * 2)   // 172032 B, W only

__device__ __forceinline__ uint32_t su32(const void* p) {
    uint32_t a;
    asm("{ .reg .u64 t; cvta.to.shared.u64 t, %1; cvt.u32.u64 %0, t; }" : "=r"(a) : "l"(p));
    return a;
}

#define LDSM4(R0, R1, R2, R3, ADDR)                                            \
    asm volatile("ldmatrix.sync.aligned.m8n8.x4.shared.b16 {%0,%1,%2,%3}, [%4];" \
                 : "=r"(R0), "=r"(R1), "=r"(R2), "=r"(R3) : "r"(ADDR))

#define MMA(D, A0, A1, A2, A3, B0, B1)                                         \
    asm volatile("mma.sync.aligned.m16n8k16.row.col.f32.f16.f16.f32 "          \
                 "{%0,%1,%2,%3}, {%4,%5,%6,%7}, {%8,%9}, {%0,%1,%2,%3};"       \
                 : "+f"((D)[0]), "+f"((D)[1]), "+f"((D)[2]), "+f"((D)[3])      \
                 : "r"(A0), "r"(A1), "r"(A2), "r"(A3), "r"(B0), "r"(B1))

__device__ __forceinline__ float ftanh(float v) {
    float r;
    asm("tanh.approx.f32 %0, %1;" : "=f"(r) : "f"(v));
    return r;
}
__device__ __forceinline__ float fsig(float v) {
    return fmaf(0.5f, ftanh(0.5f * v), 0.5f);
}
// pack two fp32 -> fp16x2 register: lo = a, hi = b
__device__ __forceinline__ uint32_t h2u(float a, float b) {
    uint32_t u;
    asm("cvt.rn.f16x2.f32 %0, %1, %2;" : "=r"(u) : "f"(b), "f"(a));
    return u;
}
__device__ __forceinline__ uint32_t f2u(float2 v) { return h2u(v.x, v.y); }

__global__ void __launch_bounds__(TB, 1)
lstm_kernel(const float* __restrict__ x,
            const float* __restrict__ Wf, const float* __restrict__ bf_,
            const float* __restrict__ Wi, const float* __restrict__ bi_,
            const float* __restrict__ Wc, const float* __restrict__ bc_,
            const float* __restrict__ Wo, const float* __restrict__ bo_,
            float* __restrict__ out)
{
    extern __shared__ char smem[];
    const uint32_t sbase = su32(smem);
    half* const Wh = (half*)smem;

    const int tid  = threadIdx.x;
    const int lane = tid & 31, wid = tid >> 5;

    // ---- one-time init: W (K-major, gate-major rows, bias col @156, pads 0) ----
    {
        uint32_t* zw = (uint32_t*)smem;
        for (int i = tid; i < 512 * WSTR / 2; i += TB) zw[i] = 0u;
    }
    __syncthreads();
    for (int idx = tid; idx < 4 * 128 * 156; idx += TB) {
        int g = idx / 19968;
        int rem = idx - g * 19968;
        int hrow = rem / 156;
        int k = rem - hrow * 156;
        const float* Wg = (g == 0) ? Wf : (g == 1) ? Wi : (g == 2) ? Wc : Wo;
        Wh[((g << 7) + hrow) * WSTR + k] = __float2half(Wg[rem]);
    }
    for (int n = tid; n < 512; n += TB) {
        int g = n >> 7, j = n & 127;
        const float* bp = (g == 0) ? bf_ : (g == 1) ? bi_ : (g == 2) ? bc_ : bo_;
        Wh[n * WSTR + 156] = __float2half(bp[j]);
    }
    __syncthreads();

    // ---- per-thread constants ----
    const int rlo = lane >> 2;            // row within 16-row strip (low); +8 = high
    const int c0  = (lane & 3) * 2;       // frag column offset
    // B ldmatrix base: rows (lane&7)+((lane>>4)<<3), k-offset ((lane>>3)&1)*8
    const uint32_t bbase = sbase
        + (uint32_t)((lane & 7) + ((lane >> 4) << 3)) * (WSTR * 2)
        + (uint32_t)(((lane >> 3) & 1) * 8) * 2;
    // x-frag tail mode for ks=9, regs a2/a3 (cols 24+c0 / bias / pad)
    const int xdmode = (c0 < 4) ? 0 : ((c0 == 4) ? 1 : 2);
    const uint32_t XBIAS = h2u(1.0f, 0.0f);

    const int gwid = blockIdx.x * 8 + wid;

    // ================= per-warp independent recurrences =================
    #pragma unroll 1
    for (int task = gwid; task < NTASKS; task += NWARPS) {
        const size_t growlo = (size_t)task * 16 + rlo;
        const float* xlo = x + growlo * XROW;
        const float* xhi = xlo + (size_t)8 * XROW;

        uint32_t hA[8][4];                 // h_t as ready-made A fragments (fp16x2)
        #pragma unroll
        for (int i = 0; i < 8; i++)
            #pragma unroll
            for (int r = 0; r < 4; r++) hA[i][r] = 0u;
        float cst[64];
        #pragma unroll
        for (int i = 0; i < 64; i++) cst[i] = 0.0f;

        // prefetch x for t=0
        float2 pa_lo = *(const float2*)(xlo + c0);
        float2 pa_hi = *(const float2*)(xhi + c0);
        float2 pb_lo = *(const float2*)(xlo + c0 + 8);
        float2 pb_hi = *(const float2*)(xhi + c0 + 8);
        float2 pc_lo = *(const float2*)(xlo + 16 + c0);
        float2 pc_hi = *(const float2*)(xhi + 16 + c0);
        float2 pd_lo = (xdmode == 0) ? *(const float2*)(xlo + 24 + c0) : make_float2(0, 0);
        float2 pd_hi = (xdmode == 0) ? *(const float2*)(xhi + 24 + c0) : make_float2(0, 0);

        #pragma unroll 1
        for (int t = 0; t < TSTEPS; t++) {
            const bool last = (t == TSTEPS - 1);

            // pack x A-fragments for this step
            uint32_t xf8[4], xf9[4];
            xf8[0] = f2u(pa_lo); xf8[1] = f2u(pa_hi);
            xf8[2] = f2u(pb_lo); xf8[3] = f2u(pb_hi);
            xf9[0] = f2u(pc_lo); xf9[1] = f2u(pc_hi);
            xf9[2] = (xdmode == 0) ? f2u(pd_lo) : ((xdmode == 1) ? XBIAS : 0u);
            xf9[3] = (xdmode == 0) ? f2u(pd_hi) : ((xdmode == 1) ? XBIAS : 0u);

            // prefetch x for t+1 (covers full MMA+epilogue latency)
            if (!last) {
                const float* ql = xlo + (size_t)(t + 1) * 28;
                const float* qh = xhi + (size_t)(t + 1) * 28;
                pa_lo = *(const float2*)(ql + c0);      pa_hi = *(const float2*)(qh + c0);
                pb_lo = *(const float2*)(ql + c0 + 8);  pb_hi = *(const float2*)(qh + c0 + 8);
                pc_lo = *(const float2*)(ql + 16 + c0); pc_hi = *(const float2*)(qh + 16 + c0);
                if (xdmode == 0) {
                    pd_lo = *(const float2*)(ql + 24 + c0);
                    pd_hi = *(const float2*)(qh + 24 + c0);
                }
            }

            uint32_t hN[8][4];

            #pragma unroll
            for (int ch = 0; ch < 8; ch++) {
                float acc[4][2][4];        // [gate][n8][reg]
                #pragma unroll
                for (int g = 0; g < 4; g++)
                    #pragma unroll
                    for (int n8 = 0; n8 < 2; n8++)
                        #pragma unroll
                        for (int r = 0; r < 4; r++) acc[g][n8][r] = 0.0f;

                #pragma unroll
                for (int ks = 0; ks < 10; ks++) {
                    const uint32_t* A = (ks < 8) ? hA[ks] : ((ks == 8) ? xf8 : xf9);
                    #pragma unroll
                    for (int g = 0; g < 4; g++) {
                        uint32_t b0, b1, b2, b3;
                        LDSM4(b0, b1, b2, b3,
                              bbase + (uint32_t)(((g << 7) + (ch << 4)) * (WSTR * 2)
                                                 + ks * 32));
                        MMA(acc[g][0], A[0], A[1], A[2], A[3], b0, b1);
                        MMA(acc[g][1], A[0], A[1], A[2], A[3], b2, b3);
                    }
                }

                // epilogue: 16 hidden units of this chunk (j = ch*16 + n8*8 + c0 + jc)
                #pragma unroll
                for (int n8 = 0; n8 < 2; n8++) {
                    #pragma unroll
                    for (int mi = 0; mi < 2; mi++) {
                        float hv0, hv1;
                        #pragma unroll
                        for (int jc = 0; jc < 2; jc++) {
                            const int ai = mi * 2 + jc;
                            float fs = fsig(acc[0][n8][ai]);
                            float is = fsig(acc[1][n8][ai]);
                            float ns = ftanh(acc[2][n8][ai]);
                            float os = fsig(acc[3][n8][ai]);
                            const int ci = (ch << 3) + (n8 << 2) + (mi << 1) + jc;
                            float cc = fmaf(cst[ci], fs, is * ns);
                            cst[ci] = cc;
                            float hh = os * ftanh(cc);
                            if (jc == 0) hv0 = hh; else hv1 = hh;
                        }
                        if (last) {
                            const int j = (ch << 4) + (n8 << 3) + c0;
                            *(float2*)(out + (growlo + mi * 8) * HID + j) =
                                make_float2(hv0, hv1);
                        } else {
                            hN[ch][(n8 << 1) + mi] = h2u(hv0, hv1);
                        }
                    }
                }
            }

            if (!last) {
                #pragma unroll
                for (int i = 0; i < 8; i++)
                    #pragma unroll
                    for (int r = 0; r < 4; r++) hA[i][r] = hN[i][r];
            }
        }
    }
}

extern "C" void kernel_launch(void* const* d_in, const int* in_sizes, int n_in,
                              void* d_out, int out_size) {
    (void)in_sizes; (void)n_in; (void)out_size;
    cudaFuncSetAttribute(lstm_kernel, cudaFuncAttributeMaxDynamicSharedMemorySize,
                         SMEM_TOTAL);
    lstm_kernel<<<GRID, TB, SMEM_TOTAL>>>(
        (const float*)d_in[0],
        (const float*)d_in[1], (const float*)d_in[2],
        (const float*)d_in[3], (const float*)d_in[4],
        (const float*)d_in[5], (const float*)d_in[6],
        (const float*)d_in[7], (const float*)d_in[8],
        (float*)d_out);
}